// round 11
// baseline (speedup 1.0000x reference)
#include <cuda_runtime.h>
#include <cuda_fp16.h>

#define NB   8
#define NP   2048
#define C1   64
#define C2   128
#define NS   64
#define RAD2 0.36f

// Scratch: per-point MLP features f[b, n, 128] in fp16 (4 MB, L2-resident)
__device__ __half g_fh[NB * NP * C2];

// ---------------------------------------------------------------------------
// Kernel 1: per-point MLP. Block = 256 threads / 64 points (grid 256, smem
// 49 KB -> 4 blocks/SM, 32 warps/SM). Warp accumulates its 8 points in one
// pass using the R7-proven inner body (unroll 2, no spills).
// ---------------------------------------------------------------------------
__global__ __launch_bounds__(256)
void mlp_kernel(const float* __restrict__ x,
                const float* __restrict__ W1,
                const float* __restrict__ b1,
                const float* __restrict__ W2,
                const float* __restrict__ b2)
{
    __shared__ float w2t[C1][C2];      // 32 KB, [k][p]
    __shared__ float h1s[64][C1];      // 16 KB
    __shared__ float xs3[64 * 3];
    __shared__ float b2s[C2];

    int tid = threadIdx.x;
    int p0  = blockIdx.x * 64;

    for (int i = tid; i < C2 * C1; i += 256) {
        int p = i >> 6, k = i & 63;
        w2t[k][p] = W2[i];
    }
    for (int i = tid; i < 64 * 3; i += 256) xs3[i] = x[p0 * 3 + i];
    if (tid < C2) b2s[tid] = b2[tid];
    __syncthreads();

    // h1 for 64 points (4096 vals / 256 threads)
    for (int i = tid; i < 64 * C1; i += 256) {
        int q = i >> 6, c = i & 63;
        float v = fmaf(W1[c * 3 + 2], xs3[q * 3 + 2],
                  fmaf(W1[c * 3 + 1], xs3[q * 3 + 1],
                  fmaf(W1[c * 3 + 0], xs3[q * 3 + 0], b1[c])));
        h1s[q][c] = fmaxf(v, 0.f);
    }
    __syncthreads();

    int warp = tid >> 5, lane = tid & 31;
    int lane4 = lane * 4;
    int q0 = warp * 8;                  // 8 points, single pass
    float4 binit = *(const float4*)&b2s[lane4];

    float4 acc[8];
    #pragma unroll
    for (int p = 0; p < 8; p++) acc[p] = binit;

    #pragma unroll 2
    for (int k = 0; k < C1; k += 4) {
        float4 w0 = *(const float4*)(w2t[k + 0] + lane4);
        float4 w1 = *(const float4*)(w2t[k + 1] + lane4);
        float4 w2 = *(const float4*)(w2t[k + 2] + lane4);
        float4 w3 = *(const float4*)(w2t[k + 3] + lane4);
        #pragma unroll
        for (int p = 0; p < 8; p++) {
            float4 h = *(const float4*)(h1s[q0 + p] + k);   // broadcast LDS
            float4 a = acc[p];
            a.x = fmaf(h.x, w0.x, a.x); a.y = fmaf(h.x, w0.y, a.y);
            a.z = fmaf(h.x, w0.z, a.z); a.w = fmaf(h.x, w0.w, a.w);
            a.x = fmaf(h.y, w1.x, a.x); a.y = fmaf(h.y, w1.y, a.y);
            a.z = fmaf(h.y, w1.z, a.z); a.w = fmaf(h.y, w1.w, a.w);
            a.x = fmaf(h.z, w2.x, a.x); a.y = fmaf(h.z, w2.y, a.y);
            a.z = fmaf(h.z, w2.z, a.z); a.w = fmaf(h.z, w2.w, a.w);
            a.x = fmaf(h.w, w3.x, a.x); a.y = fmaf(h.w, w3.y, a.y);
            a.z = fmaf(h.w, w3.z, a.z); a.w = fmaf(h.w, w3.w, a.w);
            acc[p] = a;
        }
    }

    #pragma unroll
    for (int p = 0; p < 8; p++) {
        float4 v = acc[p];
        __half2 h01 = __floats2half2_rn(fmaxf(v.x, 0.f), fmaxf(v.y, 0.f));
        __half2 h23 = __floats2half2_rn(fmaxf(v.z, 0.f), fmaxf(v.w, 0.f));
        uint2 st;
        st.x = *(unsigned*)&h01;
        st.y = *(unsigned*)&h23;
        ((uint2*)(g_fh + (size_t)(p0 + q0 + p) * C2))[lane] = st;
    }
}

// ---------------------------------------------------------------------------
// Kernel 2: ball query + fp16 max-pool. Scan reads x from L2 (no staging) and
// stores neighbor BYTE OFFSETS (j*256) parity-split, so the paired gather
// needs zero unpack ALU: half-warp h broadcast-LDS.128s 4 offsets and adds
// them to a per-lane base pointer.
// ---------------------------------------------------------------------------
__global__ __launch_bounds__(256, 6)
void group_max_kernel(const float* __restrict__ x, float* __restrict__ out)
{
    __shared__ unsigned nbrp[8][2][NS / 2];              // 2 KB: [warp][parity][slot/2]
    __shared__ float tr[8][132];                         // padded transpose buf

    int b   = blockIdx.y;
    int tid = threadIdx.x;
    int warp = tid >> 5, lane = tid & 31;
    int half = lane >> 4;      // which neighbor of a pair
    int lo   = lane & 15;      // 16B chunk within the 256B f row
    int s = blockIdx.x * 8 + warp;

    const float* xb = x + b * NP * 3;

    float cx = __ldg(&xb[s * 3 + 0]);
    float cy = __ldg(&xb[s * 3 + 1]);
    float cz = __ldg(&xb[s * 3 + 2]);
    float cs = cx * cx + cy * cy + cz * cz;

    // Scan ascending j, 64 candidates per iteration; first <=64 in-radius.
    // Slot p parity picks the array; value stored is the byte offset j*256.
    int cnt = 0;
    for (int j0 = 0; j0 < NP && cnt < NS; j0 += 64) {
        int ja = j0 + lane;
        int jb = ja + 32;
        float xa = __ldg(&xb[ja * 3 + 0]);
        float ya = __ldg(&xb[ja * 3 + 1]);
        float za = __ldg(&xb[ja * 3 + 2]);
        float xc = __ldg(&xb[jb * 3 + 0]);
        float yc = __ldg(&xb[jb * 3 + 1]);
        float zc = __ldg(&xb[jb * 3 + 2]);

        float sqa = xa * xa + ya * ya + za * za;
        float da  = cs + sqa - 2.f * (cx * xa + cy * ya + cz * za);
        bool oka = !(da > RAD2);
        unsigned ma = __ballot_sync(0xffffffffu, oka);
        int ra = __popc(ma & ((1u << lane) - 1u));
        if (oka && (cnt + ra) < NS) {
            int slot = cnt + ra;
            nbrp[warp][slot & 1][slot >> 1] = (unsigned)ja << 8;
        }
        cnt += __popc(ma);
        if (cnt > NS) cnt = NS;
        if (cnt >= NS) break;

        float sqb = xc * xc + yc * yc + zc * zc;
        float db  = cs + sqb - 2.f * (cx * xc + cy * yc + cz * zc);
        bool okb = !(db > RAD2);
        unsigned mb = __ballot_sync(0xffffffffu, okb);
        int rb = __popc(mb & ((1u << lane) - 1u));
        if (okb && (cnt + rb) < NS) {
            int slot = cnt + rb;
            nbrp[warp][slot & 1][slot >> 1] = (unsigned)jb << 8;
        }
        cnt += __popc(mb);
        if (cnt > NS) cnt = NS;
    }
    __syncwarp();

    // Paired gather: half-warp h handles slots of parity h.
    const char* fbp = (const char*)g_fh + (size_t)b * NP * 256 + lo * 16;
    __half2 m0 = __float2half2_rn(0.f);
    __half2 m1 = m0, m2 = m0, m3 = m0;

    #define HM(v) \
        m0 = __hmax2(m0, *reinterpret_cast<__half2*>(&v.x)); \
        m1 = __hmax2(m1, *reinterpret_cast<__half2*>(&v.y)); \
        m2 = __hmax2(m2, *reinterpret_cast<__half2*>(&v.z)); \
        m3 = __hmax2(m3, *reinterpret_cast<__half2*>(&v.w));

    int k = 0;
    for (; k + 8 <= cnt; k += 8) {
        uint4 off = *(const uint4*)&nbrp[warp][half][k >> 1];  // 4 offsets, 16B aligned
        uint4 v0 = *(const uint4*)(fbp + off.x);
        uint4 v1 = *(const uint4*)(fbp + off.y);
        uint4 v2 = *(const uint4*)(fbp + off.z);
        uint4 v3 = *(const uint4*)(fbp + off.w);
        HM(v0) HM(v1) HM(v2) HM(v3)
    }
    for (; k < cnt; k += 2) {
        int slot = k + half;
        if (slot > cnt - 1) slot = cnt - 1;   // duplicate row = no-op for max
        unsigned off = nbrp[warp][slot & 1][slot >> 1];
        uint4 v = *(const uint4*)(fbp + off);
        HM(v)
    }
    #undef HM

    // Merge half-warp partials (each lo owns channels lo*8 .. lo*8+7)
    #define XMAX(m) { unsigned o = __shfl_xor_sync(0xffffffffu, *(unsigned*)&m, 16); \
                      m = __hmax2(m, *reinterpret_cast<__half2*>(&o)); }
    XMAX(m0) XMAX(m1) XMAX(m2) XMAX(m3)
    #undef XMAX

    if (half == 0) {
        float2 f0 = __half22float2(m0);
        float2 f1 = __half22float2(m1);
        float2 f2 = __half22float2(m2);
        float2 f3 = __half22float2(m3);
        float* t = &tr[warp][lo * 8];
        t[0] = f0.x; t[1] = f0.y; t[2] = f1.x; t[3] = f1.y;
        t[4] = f2.x; t[5] = f2.y; t[6] = f3.x; t[7] = f3.y;
    }
    __syncthreads();

    float* ob = out + (size_t)b * C2 * NP + blockIdx.x * 8;
    for (int i = tid; i < C2 * 8; i += 256) {
        int si = i & 7;       // center within block
        int p  = i >> 3;      // channel
        ob[p * NP + si] = tr[si][p];
    }
}

extern "C" void kernel_launch(void* const* d_in, const int* in_sizes, int n_in,
                              void* d_out, int out_size)
{
    const float* x  = (const float*)d_in[0];
    const float* W1 = (const float*)d_in[1];
    const float* b1 = (const float*)d_in[2];
    const float* W2 = (const float*)d_in[3];
    const float* b2 = (const float*)d_in[4];
    float* out = (float*)d_out;

    // Kernel 1: 64 points per block -> 256 blocks
    mlp_kernel<<<(NB * NP) / 64, 256>>>(x, W1, b1, W2, b2);

    // Kernel 2: 8 centers per block, grid (256, 8)
    dim3 grid(NP / 8, NB);
    group_max_kernel<<<grid, 256>>>(x, out);
}

// round 12
// speedup vs baseline: 1.0292x; 1.0292x over previous
#include <cuda_runtime.h>
#include <cuda_fp16.h>

#define NB   8
#define NP   2048
#define C1   64
#define C2   128
#define NS   64
#define RAD2 0.36f

// Scratch: per-point MLP features f[b, n, 128] in fp16 (4 MB, L2-resident)
__device__ __half g_fh[NB * NP * C2];
// Scratch: packed coords + squared norm, written by mlp_kernel
__device__ float4 g_xq[NB * NP];

// ---------------------------------------------------------------------------
// Kernel 1: per-point MLP (exact R10 winner: 128-pt blocks, 2 passes) plus a
// free side-product: xq[p] = (x, y, z, |x|^2) for the scan kernel.
// ---------------------------------------------------------------------------
__global__ __launch_bounds__(256)
void mlp_kernel(const float* __restrict__ x,
                const float* __restrict__ W1,
                const float* __restrict__ b1,
                const float* __restrict__ W2,
                const float* __restrict__ b2)
{
    __shared__ float w2t[C1][C2];      // 32 KB, [k][p]
    __shared__ float h1s[128][C1];     // 32 KB
    __shared__ float xs3[128 * 3];
    __shared__ float b2s[C2];

    int tid = threadIdx.x;
    int p0  = blockIdx.x * 128;

    for (int i = tid; i < C2 * C1; i += 256) {
        int p = i >> 6, k = i & 63;
        w2t[k][p] = W2[i];
    }
    for (int i = tid; i < 128 * 3; i += 256) xs3[i] = x[p0 * 3 + i];
    if (tid < C2) b2s[tid] = b2[tid];
    __syncthreads();

    for (int i = tid; i < 128 * C1; i += 256) {
        int q = i >> 6, c = i & 63;
        float v = fmaf(W1[c * 3 + 2], xs3[q * 3 + 2],
                  fmaf(W1[c * 3 + 1], xs3[q * 3 + 1],
                  fmaf(W1[c * 3 + 0], xs3[q * 3 + 0], b1[c])));
        h1s[q][c] = fmaxf(v, 0.f);
    }

    // Side-product: packed coords + |x|^2 (xs3 valid since first barrier)
    if (tid < 128) {
        float a0 = xs3[tid * 3 + 0];
        float a1 = xs3[tid * 3 + 1];
        float a2 = xs3[tid * 3 + 2];
        g_xq[p0 + tid] = make_float4(a0, a1, a2, a0 * a0 + a1 * a1 + a2 * a2);
    }
    __syncthreads();

    int warp = tid >> 5, lane = tid & 31;
    int lane4 = lane * 4;
    float4 binit = *(const float4*)&b2s[lane4];

    for (int pass = 0; pass < 2; pass++) {
        int q0 = warp * 16 + pass * 8;
        float4 acc[8];
        #pragma unroll
        for (int p = 0; p < 8; p++) acc[p] = binit;

        #pragma unroll 2
        for (int k = 0; k < C1; k += 4) {
            float4 w0 = *(const float4*)(w2t[k + 0] + lane4);
            float4 w1 = *(const float4*)(w2t[k + 1] + lane4);
            float4 w2 = *(const float4*)(w2t[k + 2] + lane4);
            float4 w3 = *(const float4*)(w2t[k + 3] + lane4);
            #pragma unroll
            for (int p = 0; p < 8; p++) {
                float4 h = *(const float4*)(h1s[q0 + p] + k);
                float4 a = acc[p];
                a.x = fmaf(h.x, w0.x, a.x); a.y = fmaf(h.x, w0.y, a.y);
                a.z = fmaf(h.x, w0.z, a.z); a.w = fmaf(h.x, w0.w, a.w);
                a.x = fmaf(h.y, w1.x, a.x); a.y = fmaf(h.y, w1.y, a.y);
                a.z = fmaf(h.y, w1.z, a.z); a.w = fmaf(h.y, w1.w, a.w);
                a.x = fmaf(h.z, w2.x, a.x); a.y = fmaf(h.z, w2.y, a.y);
                a.z = fmaf(h.z, w2.z, a.z); a.w = fmaf(h.z, w2.w, a.w);
                a.x = fmaf(h.w, w3.x, a.x); a.y = fmaf(h.w, w3.y, a.y);
                a.z = fmaf(h.w, w3.z, a.z); a.w = fmaf(h.w, w3.w, a.w);
                acc[p] = a;
            }
        }

        #pragma unroll
        for (int p = 0; p < 8; p++) {
            float4 v = acc[p];
            __half2 h01 = __floats2half2_rn(fmaxf(v.x, 0.f), fmaxf(v.y, 0.f));
            __half2 h23 = __floats2half2_rn(fmaxf(v.z, 0.f), fmaxf(v.w, 0.f));
            uint2 st;
            st.x = *(unsigned*)&h01;
            st.y = *(unsigned*)&h23;
            ((uint2*)(g_fh + (size_t)(p0 + q0 + p) * C2))[lane] = st;
        }
    }
}

// ---------------------------------------------------------------------------
// Kernel 2: ball query + fp16 max-pool. R10 winner structure; scan now reads
// packed float4 xq (coalesced LDG.128, 8 wavefronts/iter vs 18) with |x|^2
// precomputed. Gather/epilogue identical to R10.
// ---------------------------------------------------------------------------
__global__ __launch_bounds__(256, 6)
void group_max_kernel(float* __restrict__ out)
{
    __shared__ unsigned short nbr[8][NS];                // 1 KB
    __shared__ float tr[8][132];                         // padded transpose buf

    int b   = blockIdx.y;
    int tid = threadIdx.x;
    int warp = tid >> 5, lane = tid & 31;
    int half = lane >> 4;      // which neighbor of a pair
    int lo   = lane & 15;      // 16B chunk within the 256B f row
    int s = blockIdx.x * 8 + warp;

    const float4* xq = g_xq + b * NP;
    float4 c = __ldg(&xq[s]);

    // Scan ascending j, 64 candidates/iter; first <=64 with dist <= R^2
    int cnt = 0;
    for (int j0 = 0; j0 < NP && cnt < NS; j0 += 64) {
        int ja = j0 + lane;
        int jb = ja + 32;
        float4 pa = __ldg(&xq[ja]);
        float4 pb = __ldg(&xq[jb]);

        float da = c.w + pa.w - 2.f * (c.x * pa.x + c.y * pa.y + c.z * pa.z);
        bool oka = !(da > RAD2);
        unsigned ma = __ballot_sync(0xffffffffu, oka);
        int ra = __popc(ma & ((1u << lane) - 1u));
        if (oka && (cnt + ra) < NS)
            nbr[warp][cnt + ra] = (unsigned short)ja;
        cnt += __popc(ma);
        if (cnt > NS) cnt = NS;
        if (cnt >= NS) break;

        float db = c.w + pb.w - 2.f * (c.x * pb.x + c.y * pb.y + c.z * pb.z);
        bool okb = !(db > RAD2);
        unsigned mb = __ballot_sync(0xffffffffu, okb);
        int rb = __popc(mb & ((1u << lane) - 1u));
        if (okb && (cnt + rb) < NS)
            nbr[warp][cnt + rb] = (unsigned short)jb;
        cnt += __popc(mb);
        if (cnt > NS) cnt = NS;
    }
    __syncwarp();

    // Paired gather: lanes 0-15 -> even neighbor, lanes 16-31 -> odd neighbor
    const uint4* fb4 = (const uint4*)(g_fh + (size_t)b * NP * C2);  // 16 uint4/row
    __half2 m0 = __float2half2_rn(0.f);
    __half2 m1 = m0, m2 = m0, m3 = m0;

    int k = 0;
    for (; k + 8 <= cnt; k += 8) {
        uint4 nw = *(const uint4*)&nbr[warp][k];   // 8 ushort indices
        int j0 = half ? (int)(nw.x >> 16) : (int)(nw.x & 0xffffu);
        int j1 = half ? (int)(nw.y >> 16) : (int)(nw.y & 0xffffu);
        int j2 = half ? (int)(nw.z >> 16) : (int)(nw.z & 0xffffu);
        int j3 = half ? (int)(nw.w >> 16) : (int)(nw.w & 0xffffu);
        uint4 v0 = fb4[j0 * 16 + lo];
        uint4 v1 = fb4[j1 * 16 + lo];
        uint4 v2 = fb4[j2 * 16 + lo];
        uint4 v3 = fb4[j3 * 16 + lo];
        #define HM(v) \
            m0 = __hmax2(m0, *reinterpret_cast<__half2*>(&v.x)); \
            m1 = __hmax2(m1, *reinterpret_cast<__half2*>(&v.y)); \
            m2 = __hmax2(m2, *reinterpret_cast<__half2*>(&v.z)); \
            m3 = __hmax2(m3, *reinterpret_cast<__half2*>(&v.w));
        HM(v0) HM(v1) HM(v2) HM(v3)
    }
    for (; k < cnt; k += 2) {
        int idx = k + half;
        if (idx > cnt - 1) idx = cnt - 1;   // duplicate row = no-op for max
        int j = nbr[warp][idx];
        uint4 v = fb4[j * 16 + lo];
        HM(v)
    }
    #undef HM

    // Merge half-warp partials (each lo owns channels lo*8 .. lo*8+7)
    #define XMAX(m) { unsigned o = __shfl_xor_sync(0xffffffffu, *(unsigned*)&m, 16); \
                      m = __hmax2(m, *reinterpret_cast<__half2*>(&o)); }
    XMAX(m0) XMAX(m1) XMAX(m2) XMAX(m3)
    #undef XMAX

    if (half == 0) {
        float2 f0 = __half22float2(m0);
        float2 f1 = __half22float2(m1);
        float2 f2 = __half22float2(m2);
        float2 f3 = __half22float2(m3);
        float* t = &tr[warp][lo * 8];
        t[0] = f0.x; t[1] = f0.y; t[2] = f1.x; t[3] = f1.y;
        t[4] = f2.x; t[5] = f2.y; t[6] = f3.x; t[7] = f3.y;
    }
    __syncthreads();

    float* ob = out + (size_t)b * C2 * NP + blockIdx.x * 8;
    for (int i = tid; i < C2 * 8; i += 256) {
        int si = i & 7;       // center within block
        int p  = i >> 3;      // channel
        ob[p * NP + si] = tr[si][p];
    }
}

extern "C" void kernel_launch(void* const* d_in, const int* in_sizes, int n_in,
                              void* d_out, int out_size)
{
    const float* x  = (const float*)d_in[0];
    const float* W1 = (const float*)d_in[1];
    const float* b1 = (const float*)d_in[2];
    const float* W2 = (const float*)d_in[3];
    const float* b2 = (const float*)d_in[4];
    float* out = (float*)d_out;

    // Kernel 1: 128 points per block -> 128 blocks
    mlp_kernel<<<(NB * NP) / 128, 256>>>(x, W1, b1, W2, b2);

    // Kernel 2: 8 centers per block, grid (256, 8)
    dim3 grid(NP / 8, NB);
    group_max_kernel<<<grid, 256>>>(out);
}